// round 1
// baseline (speedup 1.0000x reference)
#include <cuda_runtime.h>

// Problem constants
#define NB 4
#define NS 2048
#define NH 16
#define ND 64
#define NE 1024

// Scratch (device globals: allocation-free)
__device__ float g_q[NB*NH*NS*ND];     // [bh][s][d]
__device__ float g_k[NB*NH*NS*ND];
__device__ float g_v[NB*NH*NS*ND];
__device__ float g_attn[NB*NS*NE];     // [b][s][e]
__device__ float g_tw[NB*NH];

// ---------------------------------------------------------------------------
// Time weights: tw[b,h] = softmax_h(time_enc[b] @ Wt + bt)
// ---------------------------------------------------------------------------
__global__ void tw_kernel(const float* __restrict__ time_enc,
                          const float* __restrict__ Wt,
                          const float* __restrict__ bt) {
    int b = blockIdx.x;
    int h = threadIdx.x;                 // 16 threads
    float acc = bt[h];
    #pragma unroll 8
    for (int t = 0; t < 128; t++)
        acc += time_enc[b*128 + t] * Wt[t*16 + h];
    float m = acc;
    #pragma unroll
    for (int o = 8; o > 0; o >>= 1)
        m = fmaxf(m, __shfl_xor_sync(0xffffu, m, o));
    float e = expf(acc - m);
    float ssum = e;
    #pragma unroll
    for (int o = 8; o > 0; o >>= 1)
        ssum += __shfl_xor_sync(0xffffu, ssum, o);
    g_tw[b*16 + h] = e / ssum;
}

// ---------------------------------------------------------------------------
// 128x128x16 SGEMM, 256 threads, 8x8 microtile.
// mode 0: fused QKV  (grid.x = 24: mat = x>>3, ntile = x&7), scatters to
//         g_q/g_k/g_v in [bh][s][d] layout.
// mode 1: out proj   (grid.x = 8), A = g_attn, C = Cout + bias.
// ---------------------------------------------------------------------------
__global__ void __launch_bounds__(256) gemm128(
    const float* __restrict__ A,
    const float* __restrict__ W0,
    const float* __restrict__ W1,
    const float* __restrict__ W2,
    const float* __restrict__ bias,
    float* __restrict__ Cout,
    int mode)
{
    __shared__ float As[16][128];   // A^T tile, XOR-8 swizzled
    __shared__ float Bs[16][128];
    const int tid = threadIdx.x;
    const int bx = blockIdx.x, by = blockIdx.y;

    int mat, ntile;
    const float* Wp;
    if (mode == 0) {
        mat = bx >> 3; ntile = bx & 7;
        Wp = (mat == 0) ? W0 : ((mat == 1) ? W1 : W2);
    } else {
        mat = 0; ntile = bx; Wp = W0;
    }
    const float* Ap = (mode == 0) ? A : g_attn;

    const int m0 = by * 128;
    const int n0 = ntile * 128;
    const int tx = tid & 15, ty = tid >> 4;

    float acc[8][8];
    #pragma unroll
    for (int i = 0; i < 8; i++)
        #pragma unroll
        for (int j = 0; j < 8; j++) acc[i][j] = 0.f;

    const float* Abase = Ap + (size_t)m0 * 1024;
    const float* Bbase = Wp + n0;

    for (int k0 = 0; k0 < 1024; k0 += 16) {
        // Load A tile 128x16, store transposed + swizzled (conflict-free)
        #pragma unroll
        for (int i = 0; i < 2; i++) {
            int f  = tid + i * 256;         // 0..511 float4 slots
            int m  = f >> 2;
            int kq = f & 3;                 // which float4 within the 16-k row
            float4 a = *(const float4*)(Abase + (size_t)m * 1024 + k0 + kq * 4);
            int mc = m ^ (kq << 3);
            As[kq*4+0][mc] = a.x;
            As[kq*4+1][mc] = a.y;
            As[kq*4+2][mc] = a.z;
            As[kq*4+3][mc] = a.w;
        }
        // Load B tile 16x128 row-major
        #pragma unroll
        for (int i = 0; i < 2; i++) {
            int f  = tid + i * 256;
            int kk = f >> 5;
            int n4 = (f & 31) << 2;
            *(float4*)&Bs[kk][n4] =
                *(const float4*)(Bbase + (size_t)(k0 + kk) * 1024 + n4);
        }
        __syncthreads();

        #pragma unroll
        for (int k = 0; k < 16; k++) {
            int sw = (k >> 2) << 3;
            float4 a0 = *(float4*)&As[k][(ty*8) ^ sw];
            float4 a1 = *(float4*)&As[k][((ty*8) ^ sw) + 4];
            float4 b0 = *(float4*)&Bs[k][tx*8];
            float4 b1 = *(float4*)&Bs[k][tx*8 + 4];
            float av[8] = {a0.x,a0.y,a0.z,a0.w,a1.x,a1.y,a1.z,a1.w};
            float bv[8] = {b0.x,b0.y,b0.z,b0.w,b1.x,b1.y,b1.z,b1.w};
            #pragma unroll
            for (int i = 0; i < 8; i++)
                #pragma unroll
                for (int j = 0; j < 8; j++)
                    acc[i][j] = fmaf(av[i], bv[j], acc[i][j]);
        }
        __syncthreads();
    }

    if (mode == 0) {
        float* outp = (mat == 0) ? g_q : ((mat == 1) ? g_k : g_v);
        #pragma unroll
        for (int i = 0; i < 8; i++) {
            int row = m0 + ty*8 + i;
            int b = row >> 11, s = row & 2047;
            #pragma unroll
            for (int jj = 0; jj < 8; jj += 4) {
                int col = n0 + tx*8 + jj;
                int h = col >> 6, d = col & 63;
                float4 v = make_float4(acc[i][jj], acc[i][jj+1],
                                       acc[i][jj+2], acc[i][jj+3]);
                *(float4*)&outp[(((size_t)(b*16+h)*2048 + s)*64 + d)] = v;
            }
        }
    } else {
        #pragma unroll
        for (int i = 0; i < 8; i++) {
            int row = m0 + ty*8 + i;
            #pragma unroll
            for (int jj = 0; jj < 8; jj += 4) {
                int col = n0 + tx*8 + jj;
                float4 v = make_float4(acc[i][jj]   + bias[col],
                                       acc[i][jj+1] + bias[col+1],
                                       acc[i][jj+2] + bias[col+2],
                                       acc[i][jj+3] + bias[col+3]);
                *(float4*)&Cout[(size_t)row * 1024 + col] = v;
            }
        }
    }
}

// ---------------------------------------------------------------------------
// Flash attention. Block = 256 threads, 128 q-rows x full D=64.
// KV tiles of 128. Q/K stored transposed in smem (XOR-8 swizzle);
// scores tile (P) staged in smem for the PV GEMM.
// Epilogue writes [b][s][e] into g_attn.
// ---------------------------------------------------------------------------
__global__ void __launch_bounds__(256) flash_kernel() {
    extern __shared__ float sm[];
    float* Qt = sm;              // [64][128]   8192 floats
    float* Kt = sm + 8192;       // [64][128]
    float* Vs = sm + 16384;      // [128][64]
    float* Ps = sm + 24576;      // [128][128] 16384 floats

    const int tid = threadIdx.x;
    const int qt = blockIdx.x;
    const int bh = blockIdx.y;
    const int tx = tid & 15, ty = tid >> 4;

    const float* qg = g_q + ((size_t)bh * 2048 + qt * 128) * 64;
    const float* kg = g_k + (size_t)bh * 2048 * 64;
    const float* vg = g_v + (size_t)bh * 2048 * 64;
    const float cs = g_tw[bh] * 0.125f;   // 1/sqrt(64) * time weight

    // Load Q tile transposed+swizzled
    #pragma unroll
    for (int i = 0; i < 8; i++) {
        int f = tid + i * 256;       // 0..2047 float4 slots
        int r = f >> 4;
        int dq = f & 15;
        float4 a = *(const float4*)(qg + r * 64 + dq * 4);
        int rc = r ^ ((dq & 3) << 3);
        Qt[(dq*4+0)*128 + rc] = a.x;
        Qt[(dq*4+1)*128 + rc] = a.y;
        Qt[(dq*4+2)*128 + rc] = a.z;
        Qt[(dq*4+3)*128 + rc] = a.w;
    }

    float m_i[8], l_i[8], acc[8][4];
    #pragma unroll
    for (int i = 0; i < 8; i++) {
        m_i[i] = -1e30f; l_i[i] = 0.f;
        acc[i][0] = acc[i][1] = acc[i][2] = acc[i][3] = 0.f;
    }
    __syncthreads();

    for (int kt = 0; kt < 16; kt++) {
        const float* kgt = kg + kt * 128 * 64;
        const float* vgt = vg + kt * 128 * 64;
        #pragma unroll
        for (int i = 0; i < 8; i++) {
            int f = tid + i * 256;
            int r = f >> 4;
            int dq = f & 15;
            float4 a = *(const float4*)(kgt + r * 64 + dq * 4);
            int rc = r ^ ((dq & 3) << 3);
            Kt[(dq*4+0)*128 + rc] = a.x;
            Kt[(dq*4+1)*128 + rc] = a.y;
            Kt[(dq*4+2)*128 + rc] = a.z;
            Kt[(dq*4+3)*128 + rc] = a.w;
            *(float4*)(Vs + f * 4) = *(const float4*)(vgt + f * 4);
        }
        __syncthreads();

        // GEMM1: S = Q K^T  (8x8 per thread)
        float sreg[8][8];
        #pragma unroll
        for (int i = 0; i < 8; i++)
            #pragma unroll
            for (int j = 0; j < 8; j++) sreg[i][j] = 0.f;

        #pragma unroll 8
        for (int d = 0; d < 64; d++) {
            int sw = ((d >> 2) & 3) << 3;
            float4 a0 = *(float4*)&Qt[d*128 + ((ty*8) ^ sw)];
            float4 a1 = *(float4*)&Qt[d*128 + ((ty*8) ^ sw) + 4];
            float4 b0 = *(float4*)&Kt[d*128 + ((tx*8) ^ sw)];
            float4 b1 = *(float4*)&Kt[d*128 + ((tx*8) ^ sw) + 4];
            float av[8] = {a0.x,a0.y,a0.z,a0.w,a1.x,a1.y,a1.z,a1.w};
            float bv[8] = {b0.x,b0.y,b0.z,b0.w,b1.x,b1.y,b1.z,b1.w};
            #pragma unroll
            for (int i = 0; i < 8; i++)
                #pragma unroll
                for (int j = 0; j < 8; j++)
                    sreg[i][j] = fmaf(av[i], bv[j], sreg[i][j]);
        }

        // Online softmax update (row stats across 16-lane groups)
        #pragma unroll
        for (int i = 0; i < 8; i++) {
            float mx = -1e30f;
            #pragma unroll
            for (int j = 0; j < 8; j++) {
                sreg[i][j] *= cs;
                mx = fmaxf(mx, sreg[i][j]);
            }
            mx = fmaxf(mx, __shfl_xor_sync(0xffffffffu, mx, 1));
            mx = fmaxf(mx, __shfl_xor_sync(0xffffffffu, mx, 2));
            mx = fmaxf(mx, __shfl_xor_sync(0xffffffffu, mx, 4));
            mx = fmaxf(mx, __shfl_xor_sync(0xffffffffu, mx, 8));
            float mnew = fmaxf(m_i[i], mx);
            float alpha = __expf(m_i[i] - mnew);
            m_i[i] = mnew;
            float rs = 0.f;
            #pragma unroll
            for (int j = 0; j < 8; j++) {
                float p = __expf(sreg[i][j] - mnew);
                sreg[i][j] = p;
                rs += p;
            }
            rs += __shfl_xor_sync(0xffffffffu, rs, 1);
            rs += __shfl_xor_sync(0xffffffffu, rs, 2);
            rs += __shfl_xor_sync(0xffffffffu, rs, 4);
            rs += __shfl_xor_sync(0xffffffffu, rs, 8);
            l_i[i] = l_i[i] * alpha + rs;
            acc[i][0] *= alpha; acc[i][1] *= alpha;
            acc[i][2] *= alpha; acc[i][3] *= alpha;
            *(float4*)&Ps[(ty*8+i)*128 + tx*8] =
                make_float4(sreg[i][0], sreg[i][1], sreg[i][2], sreg[i][3]);
            *(float4*)&Ps[(ty*8+i)*128 + tx*8 + 4] =
                make_float4(sreg[i][4], sreg[i][5], sreg[i][6], sreg[i][7]);
        }
        __syncthreads();

        // GEMM2: acc += P @ V  (8 rows x 4 cols per thread)
        #pragma unroll 4
        for (int k = 0; k < 128; k += 4) {
            float4 b0 = *(float4*)&Vs[(k+0)*64 + tx*4];
            float4 b1 = *(float4*)&Vs[(k+1)*64 + tx*4];
            float4 b2 = *(float4*)&Vs[(k+2)*64 + tx*4];
            float4 b3 = *(float4*)&Vs[(k+3)*64 + tx*4];
            #pragma unroll
            for (int i = 0; i < 8; i++) {
                float4 a = *(float4*)&Ps[(ty*8+i)*128 + k];
                acc[i][0] = fmaf(a.x, b0.x, fmaf(a.y, b1.x, fmaf(a.z, b2.x, fmaf(a.w, b3.x, acc[i][0]))));
                acc[i][1] = fmaf(a.x, b0.y, fmaf(a.y, b1.y, fmaf(a.z, b2.y, fmaf(a.w, b3.y, acc[i][1]))));
                acc[i][2] = fmaf(a.x, b0.z, fmaf(a.y, b1.z, fmaf(a.z, b2.z, fmaf(a.w, b3.z, acc[i][2]))));
                acc[i][3] = fmaf(a.x, b0.w, fmaf(a.y, b1.w, fmaf(a.z, b2.w, fmaf(a.w, b3.w, acc[i][3]))));
            }
        }
        __syncthreads();
    }

    // Epilogue: normalize, write [b][s][e]
    const int b = bh >> 4, h = bh & 15;
    #pragma unroll
    for (int i = 0; i < 8; i++) {
        float inv = 1.0f / l_i[i];
        int srow = qt * 128 + ty*8 + i;
        float4 o = make_float4(acc[i][0]*inv, acc[i][1]*inv,
                               acc[i][2]*inv, acc[i][3]*inv);
        *(float4*)&g_attn[((size_t)(b*2048 + srow) * 1024) + h*64 + tx*4] = o;
    }
}

// ---------------------------------------------------------------------------
extern "C" void kernel_launch(void* const* d_in, const int* in_sizes, int n_in,
                              void* d_out, int out_size) {
    const float* x  = (const float*)d_in[0];
    const float* te = (const float*)d_in[1];
    const float* Wq = (const float*)d_in[2];
    const float* Wk = (const float*)d_in[3];
    const float* Wv = (const float*)d_in[4];
    const float* Wo = (const float*)d_in[5];
    const float* bo = (const float*)d_in[6];
    const float* Wt = (const float*)d_in[7];
    const float* bt = (const float*)d_in[8];
    float* out = (float*)d_out;

    cudaFuncSetAttribute(flash_kernel,
                         cudaFuncAttributeMaxDynamicSharedMemorySize, 160*1024);

    tw_kernel<<<NB, NH>>>(te, Wt, bt);
    gemm128<<<dim3(24, 64), 256>>>(x, Wq, Wk, Wv, nullptr, nullptr, 0);
    flash_kernel<<<dim3(16, 64), 256, 160*1024>>>();
    gemm128<<<dim3(8, 64), 256>>>(nullptr, Wo, nullptr, nullptr, bo, out, 1);
}